// round 16
// baseline (speedup 1.0000x reference)
#include <cuda_runtime.h>
#include <math.h>
#include <stdint.h>

#define NSEG 1024
#define DIN 16
#define HEADS 4
#define DOT 64

// ---------------- device scratch ----------------
__device__ float g_Weff[DIN * HEADS];
__device__ int   g_bnd[NSEG + 1];

// ---------------- K1: segment boundaries + Weff (log2e-folded) ----------------
__global__ void k_prep(const int* __restrict__ seg, int n,
                       const float* __restrict__ Wk, const float* __restrict__ Wq)
{
    int gt = blockIdx.x * blockDim.x + threadIdx.x;
    int gs = gridDim.x * blockDim.x;

    // Weff = Wk[:16] . Wq / sqrt(64) * log2(e)  (agg rows cancel in softmax;
    // log2e folded so the kernel uses a bare exp2f)
    if (blockIdx.x == 0 && threadIdx.x < DIN * HEADS) {
        int i = threadIdx.x >> 2, h = threadIdx.x & 3;
        float s = 0.f;
        #pragma unroll 8
        for (int d = 0; d < DOT; d++)
            s = fmaf(Wk[i * (DOT * HEADS) + h * DOT + d], Wq[h * DOT + d], s);
        g_Weff[threadIdx.x] = s * (0.125f * 1.4426950408889634f);
    }

    for (int i = gt; i < n; i += gs) {
        int si = seg[i];
        int sp = (i == 0) ? -1 : seg[i - 1];
        if (si != sp)
            for (int s = sp + 1; s <= si; s++) g_bnd[s] = i;
        if (i == n - 1)
            for (int s = si + 1; s <= NSEG; s++) g_bnd[s] = n;
    }
}

// ---------------- K2: per-segment softmax, recompute-exp, low-reg ----------------
// pre = x.Weff2 (log2 domain), e = exp2(pre). No max subtraction (logits O(1),
// shift-invariant). Phase 2 recomputes e from L1-resident inputs instead of
// holding them in registers -> regs ~40 -> 6 CTAs/SM.
#define SMX_THREADS 256
__global__ void __launch_bounds__(SMX_THREADS, 6)
k_smx(const float* __restrict__ in, float* __restrict__ out, int n)
{
    __shared__ int bnd[2];
    __shared__ float sWe[DIN * HEADS];
    __shared__ float red[8 * HEADS];
    __shared__ float s_stat[HEADS];

    int s = blockIdx.x;
    int t = threadIdx.x;
    if (t < 2) bnd[t] = g_bnd[s + t];
    if (t < DIN * HEADS) sWe[t] = g_Weff[t];
    __syncthreads();

    int lo = bnd[0], hi = bnd[1];
    if (hi <= lo) return;

    int wid = t >> 5, lid = t & 31;

    // phase 1: accumulate per-head exp sums (chunked dot, no big arrays)
    float sum[HEADS] = {0.f, 0.f, 0.f, 0.f};
    for (int i = lo + t; i < hi; i += SMX_THREADS) {
        float p[HEADS] = {0.f, 0.f, 0.f, 0.f};
        const float4* row = (const float4*)&in[(size_t)i * DIN];
        #pragma unroll
        for (int q = 0; q < 4; q++) {
            float4 x = row[q];
            #pragma unroll
            for (int h = 0; h < HEADS; h++) {
                p[h] = fmaf(x.x, sWe[(4 * q + 0) * HEADS + h], p[h]);
                p[h] = fmaf(x.y, sWe[(4 * q + 1) * HEADS + h], p[h]);
                p[h] = fmaf(x.z, sWe[(4 * q + 2) * HEADS + h], p[h]);
                p[h] = fmaf(x.w, sWe[(4 * q + 3) * HEADS + h], p[h]);
            }
        }
        #pragma unroll
        for (int h = 0; h < HEADS; h++) sum[h] += exp2f(p[h]);
    }

    // block reduction of sums
    #pragma unroll
    for (int h = 0; h < HEADS; h++)
        for (int o = 16; o; o >>= 1) sum[h] += __shfl_xor_sync(0xffffffffu, sum[h], o);
    if (lid == 0)
        #pragma unroll
        for (int h = 0; h < HEADS; h++) red[wid * HEADS + h] = sum[h];
    __syncthreads();
    if (t < HEADS) {
        float v = 0.f;
        for (int ww = 0; ww < 8; ww++) v += red[ww * HEADS + t];
        s_stat[t] = v;
    }
    __syncthreads();
    float inv[HEADS];
    #pragma unroll
    for (int h = 0; h < HEADS; h++) inv[h] = 1.0f / s_stat[h];

    // phase 2: recompute e (inputs are L1-resident) and write normalized
    for (int i = lo + t; i < hi; i += SMX_THREADS) {
        float p[HEADS] = {0.f, 0.f, 0.f, 0.f};
        const float4* row = (const float4*)&in[(size_t)i * DIN];
        #pragma unroll
        for (int q = 0; q < 4; q++) {
            float4 x = row[q];
            #pragma unroll
            for (int h = 0; h < HEADS; h++) {
                p[h] = fmaf(x.x, sWe[(4 * q + 0) * HEADS + h], p[h]);
                p[h] = fmaf(x.y, sWe[(4 * q + 1) * HEADS + h], p[h]);
                p[h] = fmaf(x.z, sWe[(4 * q + 2) * HEADS + h], p[h]);
                p[h] = fmaf(x.w, sWe[(4 * q + 3) * HEADS + h], p[h]);
            }
        }
        float4 o;
        o.x = exp2f(p[0]) * inv[0];
        o.y = exp2f(p[1]) * inv[1];
        o.z = exp2f(p[2]) * inv[2];
        o.w = exp2f(p[3]) * inv[3];
        *(float4*)&out[(size_t)i * HEADS] = o;
    }
}

// ---------------- launch ----------------
extern "C" void kernel_launch(void* const* d_in, const int* in_sizes, int n_in,
                              void* d_out, int out_size)
{
    const float* inputs = (const float*)d_in[0];
    const int*   seg    = (const int*)d_in[1];
    // d_in[2] lengths: unused by reference computation
    // d_in[3..10]: MLP/rho weights — cancel exactly in the per-segment softmax
    const float* Wk = (const float*)d_in[11];
    const float* Wq = (const float*)d_in[12];
    float* out = (float*)d_out;

    int n = in_sizes[0] / DIN;

    k_prep<<<304, 256>>>(seg, n, Wk, Wq);
    k_smx<<<NSEG, SMX_THREADS>>>(inputs, out, n);
}

// round 17
// speedup vs baseline: 2.0947x; 2.0947x over previous
#include <cuda_runtime.h>
#include <math.h>
#include <stdint.h>

#define NPTS_MAX 500000
#define NSEG 1024
#define DIN 16
#define HEADS 4
#define DOT 64

// ---------------- device scratch ----------------
__device__ float g_Weff[DIN * HEADS];
__device__ int   g_bnd[NSEG + 1];
__device__ float g_pre[NPTS_MAX * HEADS];   // fallback for oversized segments

// ---------------- K1: segment boundaries + Weff (log2e-folded) ----------------
__global__ void k_prep(const int* __restrict__ seg, int n,
                       const float* __restrict__ Wk, const float* __restrict__ Wq)
{
    int gt = blockIdx.x * blockDim.x + threadIdx.x;
    int gs = gridDim.x * blockDim.x;

    // Weff = Wk[:16] . Wq / sqrt(64) * log2(e)  (agg rows cancel in softmax)
    if (blockIdx.x == 0 && threadIdx.x < DIN * HEADS) {
        int i = threadIdx.x >> 2, h = threadIdx.x & 3;
        float s = 0.f;
        #pragma unroll 8
        for (int d = 0; d < DOT; d++)
            s = fmaf(Wk[i * (DOT * HEADS) + h * DOT + d], Wq[h * DOT + d], s);
        g_Weff[threadIdx.x] = s * (0.125f * 1.4426950408889634f);
    }

    for (int i = gt; i < n; i += gs) {
        int si = seg[i];
        int sp = (i == 0) ? -1 : seg[i - 1];
        if (si != sp)
            for (int s = sp + 1; s <= si; s++) g_bnd[s] = i;
        if (i == n - 1)
            for (int s = si + 1; s <= NSEG; s++) g_bnd[s] = n;
    }
}

// ---------------- K2: per-segment softmax, single-read, registers-held exps ----------
// No max subtraction (logits O(1), softmax shift-invariant). Exps held in
// prc[4][4]; input read exactly once. No xv staging array -> ~48 regs -> 5 CTAs/SM.
#define SMX_THREADS 256
__global__ void __launch_bounds__(SMX_THREADS, 5)
k_smx(const float* __restrict__ in, float* __restrict__ out, int n)
{
    __shared__ int bnd[2];
    __shared__ float sWe[DIN * HEADS];
    __shared__ float red[8 * HEADS];
    __shared__ float s_stat[HEADS];

    int s = blockIdx.x;
    int t = threadIdx.x;
    if (t < 2) bnd[t] = g_bnd[s + t];
    if (t < DIN * HEADS) sWe[t] = g_Weff[t];
    __syncthreads();

    int lo = bnd[0], hi = bnd[1];
    int cnt = hi - lo;
    if (cnt <= 0) return;

    int wid = t >> 5, lid = t & 31;
    bool incore = (cnt <= 4 * SMX_THREADS);

    float prc[4][HEADS];
    float sum[HEADS] = {0.f, 0.f, 0.f, 0.f};

    // phase 1: e = exp2(x.Weff2), hold in registers, accumulate sums
    if (incore) {
        #pragma unroll
        for (int it = 0; it < 4; it++) {
            int i = lo + t + it * SMX_THREADS;
            if (i < hi) {
                float p[HEADS] = {0.f, 0.f, 0.f, 0.f};
                const float4* row = (const float4*)&in[(size_t)i * DIN];
                #pragma unroll
                for (int q = 0; q < 4; q++) {
                    float4 x = row[q];
                    #pragma unroll
                    for (int h = 0; h < HEADS; h++) {
                        p[h] = fmaf(x.x, sWe[(4 * q + 0) * HEADS + h], p[h]);
                        p[h] = fmaf(x.y, sWe[(4 * q + 1) * HEADS + h], p[h]);
                        p[h] = fmaf(x.z, sWe[(4 * q + 2) * HEADS + h], p[h]);
                        p[h] = fmaf(x.w, sWe[(4 * q + 3) * HEADS + h], p[h]);
                    }
                }
                #pragma unroll
                for (int h = 0; h < HEADS; h++) {
                    float e = exp2f(p[h]);
                    prc[it][h] = e;
                    sum[h] += e;
                }
            } else {
                #pragma unroll
                for (int h = 0; h < HEADS; h++) prc[it][h] = 0.f;
            }
        }
    } else {
        for (int i = lo + t; i < hi; i += SMX_THREADS) {
            float p[HEADS] = {0.f, 0.f, 0.f, 0.f};
            const float4* row = (const float4*)&in[(size_t)i * DIN];
            #pragma unroll
            for (int q = 0; q < 4; q++) {
                float4 x = row[q];
                #pragma unroll
                for (int h = 0; h < HEADS; h++) {
                    p[h] = fmaf(x.x, sWe[(4 * q + 0) * HEADS + h], p[h]);
                    p[h] = fmaf(x.y, sWe[(4 * q + 1) * HEADS + h], p[h]);
                    p[h] = fmaf(x.z, sWe[(4 * q + 2) * HEADS + h], p[h]);
                    p[h] = fmaf(x.w, sWe[(4 * q + 3) * HEADS + h], p[h]);
                }
            }
            #pragma unroll
            for (int h = 0; h < HEADS; h++) {
                float e = exp2f(p[h]);
                g_pre[(size_t)i * HEADS + h] = e;
                sum[h] += e;
            }
        }
    }

    // block reduction of sums
    #pragma unroll
    for (int h = 0; h < HEADS; h++)
        for (int o = 16; o; o >>= 1) sum[h] += __shfl_xor_sync(0xffffffffu, sum[h], o);
    if (lid == 0)
        #pragma unroll
        for (int h = 0; h < HEADS; h++) red[wid * HEADS + h] = sum[h];
    __syncthreads();
    if (t < HEADS) {
        float v = 0.f;
        for (int ww = 0; ww < 8; ww++) v += red[ww * HEADS + t];
        s_stat[t] = v;
    }
    __syncthreads();
    float inv[HEADS];
    #pragma unroll
    for (int h = 0; h < HEADS; h++) inv[h] = 1.0f / s_stat[h];

    // phase 2: normalize + write
    if (incore) {
        #pragma unroll
        for (int it = 0; it < 4; it++) {
            int i = lo + t + it * SMX_THREADS;
            if (i < hi) {
                float4 o;
                o.x = prc[it][0] * inv[0];
                o.y = prc[it][1] * inv[1];
                o.z = prc[it][2] * inv[2];
                o.w = prc[it][3] * inv[3];
                *(float4*)&out[(size_t)i * HEADS] = o;
            }
        }
    } else {
        for (int i = lo + t; i < hi; i += SMX_THREADS) {
            #pragma unroll
            for (int h = 0; h < HEADS; h++)
                out[(size_t)i * HEADS + h] = g_pre[(size_t)i * HEADS + h] * inv[h];
        }
    }
}

// ---------------- launch ----------------
extern "C" void kernel_launch(void* const* d_in, const int* in_sizes, int n_in,
                              void* d_out, int out_size)
{
    const float* inputs = (const float*)d_in[0];
    const int*   seg    = (const int*)d_in[1];
    // d_in[2] lengths: unused by reference computation
    // d_in[3..10]: MLP/rho weights — cancel exactly in the per-segment softmax
    const float* Wk = (const float*)d_in[11];
    const float* Wq = (const float*)d_in[12];
    float* out = (float*)d_out;

    int n = in_sizes[0] / DIN;

    k_prep<<<304, 256>>>(seg, n, Wk, Wq);
    k_smx<<<NSEG, SMX_THREADS>>>(inputs, out, n);
}